// round 1
// baseline (speedup 1.0000x reference)
#include <cuda_runtime.h>

#define DIM 1024
#define NHEADS 16
#define HDIM 64
#define BATCH 2
#define SEQ 2048
#define NROPE 2043
#define PREFIX (SEQ - NROPE)   // 5
#define MTOT (BATCH * SEQ)     // 4096

// Scratch (64 MB total) — __device__ globals per allocation rules.
__device__ float g_q[BATCH * NHEADS * SEQ * HDIM];
__device__ float g_k[BATCH * NHEADS * SEQ * HDIM];
__device__ float g_v[BATCH * NHEADS * SEQ * HDIM];
__device__ float g_o[BATCH * SEQ * DIM];

// ---------------------------------------------------------------------------
// GEMM 1: qkv = x[4096,1024] @ W_qkv[1024,3072], scatter epilogue into
// q/k/v buffers laid out [B, H, N, HD].
// ---------------------------------------------------------------------------
__global__ __launch_bounds__(256) void qkv_gemm_kernel(
    const float* __restrict__ A, const float* __restrict__ Bm)
{
    __shared__ __align__(16) float As[16][68];  // As[k][m] (transposed)
    __shared__ __align__(16) float Bs[16][68];  // Bs[k][e]

    const int tx = threadIdx.x;        // 0..15
    const int ty = threadIdx.y;        // 0..15
    const int tid = ty * 16 + tx;
    const int e0 = blockIdx.x * 64;
    const int m0 = blockIdx.y * 64;

    float acc[4][4] = {};

    for (int k0 = 0; k0 < DIM; k0 += 16) {
#pragma unroll
        for (int r = 0; r < 4; r++) {
            int idx = tid + r * 256;
            int kl = idx & 15, ml = idx >> 4;
            As[kl][ml] = A[(size_t)(m0 + ml) * DIM + k0 + kl];
        }
#pragma unroll
        for (int r = 0; r < 4; r++) {
            int idx = tid + r * 256;
            int el = idx & 63, kl = idx >> 6;
            Bs[kl][el] = Bm[(size_t)(k0 + kl) * (3 * DIM) + e0 + el];
        }
        __syncthreads();
#pragma unroll
        for (int k = 0; k < 16; k++) {
            float4 a4 = *(const float4*)&As[k][ty * 4];
            float4 b4 = *(const float4*)&Bs[k][tx * 4];
            float av[4] = {a4.x, a4.y, a4.z, a4.w};
            float bv[4] = {b4.x, b4.y, b4.z, b4.w};
#pragma unroll
            for (int i = 0; i < 4; i++)
#pragma unroll
                for (int j = 0; j < 4; j++)
                    acc[i][j] += av[i] * bv[j];
        }
        __syncthreads();
    }

    // Scatter epilogue. Per-block constants: which (q/k/v), head, batch.
    const int which = e0 >> 10;           // 0,1,2
    const int h     = (e0 >> 6) & 15;
    const int bb    = m0 >> 11;
    const int nbase = m0 & (SEQ - 1);
    float* dst = (which == 0 ? g_q : (which == 1 ? g_k : g_v));
    dst += ((size_t)(bb * NHEADS + h)) * SEQ * HDIM;

#pragma unroll
    for (int i = 0; i < 4; i++) {
        int n = nbase + 4 * ty + i;
#pragma unroll
        for (int j = 0; j < 4; j++) {
            int hd = 4 * tx + j;
            dst[(size_t)n * HDIM + hd] = acc[i][j];
        }
    }
}

// ---------------------------------------------------------------------------
// RoPE on q and k (positions n >= PREFIX). One thread per rotation pair.
// idx -> (bh, n, d) with d in [0,32).
// ---------------------------------------------------------------------------
__global__ void rope_kernel(const float* __restrict__ sinp,
                            const float* __restrict__ cosp)
{
    int idx = blockIdx.x * blockDim.x + threadIdx.x;
    if (idx >= BATCH * NHEADS * SEQ * 32) return;
    int d  = idx & 31;
    int n  = (idx >> 5) & (SEQ - 1);
    int bh = idx >> 16;                  // SEQ*32 = 65536 = 2^16
    if (n < PREFIX) return;
    int rp = n - PREFIX;
    float c1 = cosp[rp * HDIM + d];
    float c2 = cosp[rp * HDIM + d + 32];
    float s1 = sinp[rp * HDIM + d];
    float s2 = sinp[rp * HDIM + d + 32];
    size_t base = ((size_t)bh * SEQ + n) * HDIM + d;
    {
        float t1 = g_q[base], t2 = g_q[base + 32];
        g_q[base]      = t1 * c1 - t2 * s1;
        g_q[base + 32] = t2 * c2 + t1 * s2;
    }
    {
        float t1 = g_k[base], t2 = g_k[base + 32];
        g_k[base]      = t1 * c1 - t2 * s1;
        g_k[base + 32] = t2 * c2 + t1 * s2;
    }
}

// ---------------------------------------------------------------------------
// Flash attention: one CTA per (bh, 64-query tile). 256 threads as 16x16,
// each owning a 4x4 microtile of the 64x64 S / O tiles. Online softmax.
// Dynamic smem:
//   Qs [64][68]  transposed: Qs[k][r]
//   Ks [64][68]  transposed: Ks[k][c]
//   Vs [64][68]  natural:    Vs[c][d]
//   Ps [64][65]  natural:    Ps[r][c]   (odd stride -> conflict-free)
// ---------------------------------------------------------------------------
#define FA_STRIDE 68
#define FA_PSTRIDE 65
#define FA_SMEM_BYTES ((3 * 64 * FA_STRIDE + 64 * FA_PSTRIDE) * 4)

__global__ __launch_bounds__(256) void flash_attn_kernel()
{
    extern __shared__ __align__(16) float sm[];
    float* Qs = sm;
    float* Ks = Qs + 64 * FA_STRIDE;
    float* Vs = Ks + 64 * FA_STRIDE;
    float* Ps = Vs + 64 * FA_STRIDE;

    const int tid = threadIdx.x;
    const int tx = tid & 15;
    const int ty = tid >> 4;
    const int bh = blockIdx.y;
    const int i0 = blockIdx.x * 64;

    const float* qb = g_q + (size_t)bh * SEQ * HDIM;
    const float* kb = g_k + (size_t)bh * SEQ * HDIM;
    const float* vb = g_v + (size_t)bh * SEQ * HDIM;

    // Load Q tile (transposed into smem).
#pragma unroll
    for (int r = 0; r < 16; r++) {
        int idx = tid + r * 256;
        int hd = idx & 63, rr = idx >> 6;
        Qs[hd * FA_STRIDE + rr] = qb[(size_t)(i0 + rr) * HDIM + hd];
    }

    float o[4][4] = {};
    float m_run[4], l_run[4];
#pragma unroll
    for (int i = 0; i < 4; i++) { m_run[i] = -1e30f; l_run[i] = 0.0f; }
    const float scale = 0.125f;  // 64^-0.5

    for (int j0 = 0; j0 < SEQ; j0 += 64) {
        __syncthreads();  // prior iteration's PV reads of Ks/Vs/Ps done
#pragma unroll
        for (int r = 0; r < 16; r++) {
            int idx = tid + r * 256;
            int hd = idx & 63, c = idx >> 6;
            Ks[hd * FA_STRIDE + c] = kb[(size_t)(j0 + c) * HDIM + hd];
            Vs[c * FA_STRIDE + hd] = vb[(size_t)(j0 + c) * HDIM + hd];
        }
        __syncthreads();

        // S = Q @ K^T
        float s[4][4] = {};
#pragma unroll
        for (int k = 0; k < 64; k++) {
            float4 a4 = *(const float4*)&Qs[k * FA_STRIDE + 4 * ty];
            float4 b4 = *(const float4*)&Ks[k * FA_STRIDE + 4 * tx];
            float av[4] = {a4.x, a4.y, a4.z, a4.w};
            float bv[4] = {b4.x, b4.y, b4.z, b4.w};
#pragma unroll
            for (int i = 0; i < 4; i++)
#pragma unroll
                for (int j = 0; j < 4; j++)
                    s[i][j] += av[i] * bv[j];
        }

        // Online softmax per row (16 threads share a row; lanes 0..15 / 16..31).
#pragma unroll
        for (int i = 0; i < 4; i++) {
            float mx = s[i][0] * scale;
#pragma unroll
            for (int j = 1; j < 4; j++) mx = fmaxf(mx, s[i][j] * scale);
#pragma unroll
            for (int off = 1; off < 16; off <<= 1)
                mx = fmaxf(mx, __shfl_xor_sync(0xffffffffu, mx, off));
            float mnew = fmaxf(m_run[i], mx);
            float corr = __expf(m_run[i] - mnew);
            float rs = 0.0f;
#pragma unroll
            for (int j = 0; j < 4; j++) {
                float p = __expf(s[i][j] * scale - mnew);
                s[i][j] = p;
                rs += p;
            }
#pragma unroll
            for (int off = 1; off < 16; off <<= 1)
                rs += __shfl_xor_sync(0xffffffffu, rs, off);
            l_run[i] = l_run[i] * corr + rs;
            m_run[i] = mnew;
#pragma unroll
            for (int j = 0; j < 4; j++) o[i][j] *= corr;
        }

        // Stage P in smem (row-major, odd stride: conflict-free writes).
#pragma unroll
        for (int i = 0; i < 4; i++)
#pragma unroll
            for (int j = 0; j < 4; j++)
                Ps[(4 * ty + i) * FA_PSTRIDE + 4 * tx + j] = s[i][j];
        __syncthreads();

        // O += P @ V
#pragma unroll
        for (int c = 0; c < 64; c++) {
            float a0 = Ps[(4 * ty + 0) * FA_PSTRIDE + c];
            float a1 = Ps[(4 * ty + 1) * FA_PSTRIDE + c];
            float a2 = Ps[(4 * ty + 2) * FA_PSTRIDE + c];
            float a3 = Ps[(4 * ty + 3) * FA_PSTRIDE + c];
            float4 b4 = *(const float4*)&Vs[c * FA_STRIDE + 4 * tx];
            float bv[4] = {b4.x, b4.y, b4.z, b4.w};
#pragma unroll
            for (int j = 0; j < 4; j++) {
                o[0][j] += a0 * bv[j];
                o[1][j] += a1 * bv[j];
                o[2][j] += a2 * bv[j];
                o[3][j] += a3 * bv[j];
            }
        }
    }

    // Epilogue: normalize and write to [B, N, DIM].
    const int bb = bh >> 4, h = bh & 15;
#pragma unroll
    for (int i = 0; i < 4; i++) {
        float inv = 1.0f / l_run[i];
        int n = i0 + 4 * ty + i;
#pragma unroll
        for (int j = 0; j < 4; j++)
            g_o[((size_t)(bb * SEQ + n)) * DIM + h * HDIM + 4 * tx + j] =
                o[i][j] * inv;
    }
}

// ---------------------------------------------------------------------------
// GEMM 2: out = o[4096,1024] @ W_proj[1024,1024] + b_proj
// ---------------------------------------------------------------------------
__global__ __launch_bounds__(256) void proj_gemm_kernel(
    const float* __restrict__ Bm, const float* __restrict__ bias,
    float* __restrict__ C)
{
    __shared__ __align__(16) float As[16][68];
    __shared__ __align__(16) float Bs[16][68];

    const int tx = threadIdx.x;
    const int ty = threadIdx.y;
    const int tid = ty * 16 + tx;
    const int e0 = blockIdx.x * 64;
    const int m0 = blockIdx.y * 64;

    float acc[4][4] = {};

    for (int k0 = 0; k0 < DIM; k0 += 16) {
#pragma unroll
        for (int r = 0; r < 4; r++) {
            int idx = tid + r * 256;
            int kl = idx & 15, ml = idx >> 4;
            As[kl][ml] = g_o[(size_t)(m0 + ml) * DIM + k0 + kl];
        }
#pragma unroll
        for (int r = 0; r < 4; r++) {
            int idx = tid + r * 256;
            int el = idx & 63, kl = idx >> 6;
            Bs[kl][el] = Bm[(size_t)(k0 + kl) * DIM + e0 + el];
        }
        __syncthreads();
#pragma unroll
        for (int k = 0; k < 16; k++) {
            float4 a4 = *(const float4*)&As[k][ty * 4];
            float4 b4 = *(const float4*)&Bs[k][tx * 4];
            float av[4] = {a4.x, a4.y, a4.z, a4.w};
            float bv[4] = {b4.x, b4.y, b4.z, b4.w};
#pragma unroll
            for (int i = 0; i < 4; i++)
#pragma unroll
                for (int j = 0; j < 4; j++)
                    acc[i][j] += av[i] * bv[j];
        }
        __syncthreads();
    }

#pragma unroll
    for (int i = 0; i < 4; i++) {
        int m = m0 + 4 * ty + i;
#pragma unroll
        for (int j = 0; j < 4; j++) {
            int e = e0 + 4 * tx + j;
            C[(size_t)m * DIM + e] = acc[i][j] + bias[e];
        }
    }
}

// ---------------------------------------------------------------------------
extern "C" void kernel_launch(void* const* d_in, const int* in_sizes, int n_in,
                              void* d_out, int out_size)
{
    const float* x      = (const float*)d_in[0];
    const float* sinp   = (const float*)d_in[1];
    const float* cosp   = (const float*)d_in[2];
    const float* W_qkv  = (const float*)d_in[3];
    const float* W_proj = (const float*)d_in[4];
    const float* b_proj = (const float*)d_in[5];
    float* out = (float*)d_out;

    // 1. QKV GEMM with scatter into [B,H,N,HD] buffers.
    qkv_gemm_kernel<<<dim3(3 * DIM / 64, MTOT / 64), dim3(16, 16)>>>(x, W_qkv);

    // 2. RoPE on q, k.
    {
        int total = BATCH * NHEADS * SEQ * 32;
        rope_kernel<<<(total + 255) / 256, 256>>>(sinp, cosp);
    }

    // 3. Flash attention.
    static int smem_set = 0;
    if (!smem_set) {
        cudaFuncSetAttribute(flash_attn_kernel,
                             cudaFuncAttributeMaxDynamicSharedMemorySize,
                             FA_SMEM_BYTES);
        smem_set = 1;
    }
    flash_attn_kernel<<<dim3(SEQ / 64, BATCH * NHEADS), 256, FA_SMEM_BYTES>>>();

    // 4. Output projection + bias.
    proj_gemm_kernel<<<dim3(DIM / 64, MTOT / 64), dim3(16, 16)>>>(
        W_proj, b_proj, out);
}

// round 2
// speedup vs baseline: 2.4150x; 2.4150x over previous
#include <cuda_runtime.h>
#include <cstdint>

#define DIM 1024
#define NHEADS 16
#define HDIM 64
#define BATCH 2
#define SEQ 2048
#define NROPE 2043
#define PREFIX (SEQ - NROPE)   // 5
#define MTOT (BATCH * SEQ)     // 4096

// Scratch — __device__ globals per allocation rules.
__device__ float g_q[BATCH * NHEADS * SEQ * HDIM];
__device__ float g_k[BATCH * NHEADS * SEQ * HDIM];
__device__ float g_v[BATCH * NHEADS * SEQ * HDIM];
__device__ float g_o[BATCH * SEQ * DIM];

// ---------------------------------------------------------------------------
// TF32 helpers
// ---------------------------------------------------------------------------
__device__ __forceinline__ uint32_t f2tf32(float x) {
    uint32_t r;
    asm("cvt.rna.tf32.f32 %0, %1;" : "=r"(r) : "f"(x));
    return r;
}
__device__ __forceinline__ float f2tf32f(float x) {
    return __uint_as_float(f2tf32(x));
}
__device__ __forceinline__ void mma_tf32(float* c, const uint32_t* a,
                                         uint32_t b0, uint32_t b1) {
    asm volatile(
        "mma.sync.aligned.m16n8k8.row.col.f32.tf32.tf32.f32 "
        "{%0,%1,%2,%3}, {%4,%5,%6,%7}, {%8,%9}, {%0,%1,%2,%3};"
        : "+f"(c[0]), "+f"(c[1]), "+f"(c[2]), "+f"(c[3])
        : "r"(a[0]), "r"(a[1]), "r"(a[2]), "r"(a[3]), "r"(b0), "r"(b1));
}
__device__ __forceinline__ uint32_t uf(float x) { return __float_as_uint(x); }

// ---------------------------------------------------------------------------
// Generic TF32 GEMM: C[M,E] = A[M,1024] @ B[1024,E]
// Block tile 128x128, BK=16, 8 warps (4m x 2n), warp tile 32x64.
// MODE 0: A = x, E = 3072, scatter epilogue -> g_q/g_k/g_v [B,H,N,HD]
// MODE 1: A = g_o, E = 1024, epilogue adds bias -> Cout
// ---------------------------------------------------------------------------
template <int MODE>
__global__ __launch_bounds__(256) void gemm_tf32_kernel(
    const float* __restrict__ A, const float* __restrict__ Bm,
    const float* __restrict__ bias, float* __restrict__ Cout)
{
    __shared__ float As[128][20];   // [m][k], stride 20: conflict-free frags
    __shared__ float Bs[16][132];   // [k][e], stride 132

    const int tid = threadIdx.x;
    const int lane = tid & 31, w = tid >> 5;
    const int g = lane >> 2, t = lane & 3;
    const int wm = w & 3, wn = w >> 2;
    const int m0 = blockIdx.y * 128, e0 = blockIdx.x * 128;
    const int ldb = (MODE == 0) ? (3 * DIM) : DIM;
    const float* Ap = (MODE == 0) ? A : g_o;

    float acc[2][8][4];
#pragma unroll
    for (int i = 0; i < 2; i++)
#pragma unroll
        for (int j = 0; j < 8; j++)
#pragma unroll
            for (int q = 0; q < 4; q++) acc[i][j][q] = 0.0f;

    float4 areg[2], breg[2];

    auto load_g = [&](int k0) {
#pragma unroll
        for (int r = 0; r < 2; r++) {
            int idx = tid + 256 * r;
            areg[r] = *(const float4*)&Ap[(size_t)(m0 + (idx >> 2)) * DIM +
                                          k0 + (idx & 3) * 4];
        }
#pragma unroll
        for (int r = 0; r < 2; r++) {
            int idx = tid + 256 * r;
            breg[r] = *(const float4*)&Bm[(size_t)(k0 + (idx >> 5)) * ldb +
                                          e0 + (idx & 31) * 4];
        }
    };
    auto store_s = [&]() {
#pragma unroll
        for (int r = 0; r < 2; r++) {
            int idx = tid + 256 * r;
            float4 v;
            v.x = f2tf32f(areg[r].x); v.y = f2tf32f(areg[r].y);
            v.z = f2tf32f(areg[r].z); v.w = f2tf32f(areg[r].w);
            *(float4*)&As[idx >> 2][(idx & 3) * 4] = v;
        }
#pragma unroll
        for (int r = 0; r < 2; r++) {
            int idx = tid + 256 * r;
            float4 v;
            v.x = f2tf32f(breg[r].x); v.y = f2tf32f(breg[r].y);
            v.z = f2tf32f(breg[r].z); v.w = f2tf32f(breg[r].w);
            *(float4*)&Bs[idx >> 5][(idx & 31) * 4] = v;
        }
    };

    load_g(0);
    store_s();
    __syncthreads();

    for (int kt = 0; kt < DIM / 16; kt++) {
        if (kt + 1 < DIM / 16) load_g((kt + 1) * 16);

#pragma unroll
        for (int kk = 0; kk < 16; kk += 8) {
            uint32_t a[2][4];
#pragma unroll
            for (int mi = 0; mi < 2; mi++) {
                int rb = wm * 32 + mi * 16;
                a[mi][0] = uf(As[rb + g][kk + t]);
                a[mi][1] = uf(As[rb + g + 8][kk + t]);
                a[mi][2] = uf(As[rb + g][kk + t + 4]);
                a[mi][3] = uf(As[rb + g + 8][kk + t + 4]);
            }
#pragma unroll
            for (int nt = 0; nt < 8; nt++) {
                int cb = wn * 64 + nt * 8 + g;
                uint32_t b0 = uf(Bs[kk + t][cb]);
                uint32_t b1 = uf(Bs[kk + t + 4][cb]);
                mma_tf32(acc[0][nt], a[0], b0, b1);
                mma_tf32(acc[1][nt], a[1], b0, b1);
            }
        }
        __syncthreads();
        if (kt + 1 < DIM / 16) {
            store_s();
            __syncthreads();
        }
    }

    // Epilogue
#pragma unroll
    for (int mi = 0; mi < 2; mi++) {
        int row0 = m0 + wm * 32 + mi * 16 + g;
#pragma unroll
        for (int nt = 0; nt < 8; nt++) {
            int e = e0 + wn * 64 + nt * 8 + 2 * t;
            if (MODE == 0) {
                const int which = e0 >> 10;      // block fully inside one chunk
                const int h = (e >> 6) & 15;
                const int hd = e & 63;
                const int bb = row0 >> 11;
                const int n = row0 & (SEQ - 1);
                float* dst = (which == 0 ? g_q : (which == 1 ? g_k : g_v));
                size_t off = ((size_t)(bb * NHEADS + h) * SEQ + n) * HDIM + hd;
                float2 v0 = {acc[mi][nt][0], acc[mi][nt][1]};
                float2 v1 = {acc[mi][nt][2], acc[mi][nt][3]};
                *(float2*)&dst[off] = v0;
                *(float2*)&dst[off + 8 * HDIM] = v1;
            } else {
                float bx = bias[e], by = bias[e + 1];
                float2 v0 = {acc[mi][nt][0] + bx, acc[mi][nt][1] + by};
                float2 v1 = {acc[mi][nt][2] + bx, acc[mi][nt][3] + by};
                *(float2*)&Cout[(size_t)row0 * DIM + e] = v0;
                *(float2*)&Cout[(size_t)(row0 + 8) * DIM + e] = v1;
            }
        }
    }
}

// ---------------------------------------------------------------------------
// RoPE on q and k (positions n >= PREFIX), fp32 in-place.
// ---------------------------------------------------------------------------
__global__ void rope_kernel(const float* __restrict__ sinp,
                            const float* __restrict__ cosp)
{
    int idx = blockIdx.x * blockDim.x + threadIdx.x;
    if (idx >= BATCH * NHEADS * SEQ * 32) return;
    int d  = idx & 31;
    int n  = (idx >> 5) & (SEQ - 1);
    int bh = idx >> 16;
    if (n < PREFIX) return;
    int rp = n - PREFIX;
    float c1 = cosp[rp * HDIM + d];
    float c2 = cosp[rp * HDIM + d + 32];
    float s1 = sinp[rp * HDIM + d];
    float s2 = sinp[rp * HDIM + d + 32];
    size_t base = ((size_t)bh * SEQ + n) * HDIM + d;
    {
        float t1 = g_q[base], t2 = g_q[base + 32];
        g_q[base]      = t1 * c1 - t2 * s1;
        g_q[base + 32] = t2 * c2 + t1 * s2;
    }
    {
        float t1 = g_k[base], t2 = g_k[base + 32];
        g_k[base]      = t1 * c1 - t2 * s1;
        g_k[base + 32] = t2 * c2 + t1 * s2;
    }
}

// ---------------------------------------------------------------------------
// Flash attention, TF32 tensor cores.
// CTA: 256 threads = 8 warps; q-tile 128 rows (16 per warp); KV tiles of 64.
// smem: Qs[128][68], Ks[64][68], Vs[64][68], Ps[8][16][68] (per-warp).
// ---------------------------------------------------------------------------
#define FA_SM_FLOATS (128 * 68 + 64 * 68 + 64 * 68 + 8 * 16 * 68)
#define FA_SM_BYTES (FA_SM_FLOATS * 4)

__global__ __launch_bounds__(256, 1) void flash_tf32_kernel()
{
    extern __shared__ float sm[];
    float* Qs = sm;                      // [row][d]   stride 68
    float* Ks = Qs + 128 * 68;           // [key][d]   stride 68
    float* Vs = Ks + 64 * 68;            // [key][d]   stride 68
    const int tid = threadIdx.x;
    const int lane = tid & 31, w = tid >> 5;
    const int g = lane >> 2, t = lane & 3;
    float* Pw = Vs + 64 * 68 + w * 16 * 68;  // per-warp P [16][68]

    const int bh = blockIdx.y;
    const int i0 = blockIdx.x * 128;
    const float* qb = g_q + (size_t)bh * SEQ * HDIM;
    const float* kb = g_k + (size_t)bh * SEQ * HDIM;
    const float* vb = g_v + (size_t)bh * SEQ * HDIM;

    // Load Q tile (cvt to tf32).
#pragma unroll
    for (int r = 0; r < 8; r++) {
        int idx = tid + 256 * r;
        int row = idx >> 4, col = (idx & 15) * 4;
        float4 v = *(const float4*)&qb[(size_t)(i0 + row) * HDIM + col];
        v.x = f2tf32f(v.x); v.y = f2tf32f(v.y);
        v.z = f2tf32f(v.z); v.w = f2tf32f(v.w);
        *(float4*)&Qs[row * 68 + col] = v;
    }

    float o[8][4];
#pragma unroll
    for (int nt = 0; nt < 8; nt++)
#pragma unroll
        for (int q = 0; q < 4; q++) o[nt][q] = 0.0f;
    float mrow0 = -1e30f, mrow1 = -1e30f, lrow0 = 0.0f, lrow1 = 0.0f;
    const float scale = 0.125f;
    const int qb0 = w * 16;

    for (int j0 = 0; j0 < SEQ; j0 += 64) {
        float4 kr[4], vr[4];
#pragma unroll
        for (int r = 0; r < 4; r++) {
            int idx = tid + 256 * r;
            int row = idx >> 4, col = (idx & 15) * 4;
            kr[r] = *(const float4*)&kb[(size_t)(j0 + row) * HDIM + col];
            vr[r] = *(const float4*)&vb[(size_t)(j0 + row) * HDIM + col];
        }
        __syncthreads();   // prior iteration's smem reads complete
#pragma unroll
        for (int r = 0; r < 4; r++) {
            int idx = tid + 256 * r;
            int row = idx >> 4, col = (idx & 15) * 4;
            float4 kv = kr[r], vv = vr[r];
            kv.x = f2tf32f(kv.x); kv.y = f2tf32f(kv.y);
            kv.z = f2tf32f(kv.z); kv.w = f2tf32f(kv.w);
            vv.x = f2tf32f(vv.x); vv.y = f2tf32f(vv.y);
            vv.z = f2tf32f(vv.z); vv.w = f2tf32f(vv.w);
            *(float4*)&Ks[row * 68 + col] = kv;
            *(float4*)&Vs[row * 68 + col] = vv;
        }
        __syncthreads();

        // S = Q @ K^T  (warp rows qb0..qb0+15, all 64 keys)
        float c[8][4];
#pragma unroll
        for (int nt = 0; nt < 8; nt++)
#pragma unroll
            for (int q = 0; q < 4; q++) c[nt][q] = 0.0f;
#pragma unroll
        for (int kt = 0; kt < 8; kt++) {
            int kk = kt * 8;
            uint32_t a[4];
            a[0] = uf(Qs[(qb0 + g) * 68 + kk + t]);
            a[1] = uf(Qs[(qb0 + g + 8) * 68 + kk + t]);
            a[2] = uf(Qs[(qb0 + g) * 68 + kk + t + 4]);
            a[3] = uf(Qs[(qb0 + g + 8) * 68 + kk + t + 4]);
#pragma unroll
            for (int nt = 0; nt < 8; nt++) {
                uint32_t b0 = uf(Ks[(nt * 8 + g) * 68 + kk + t]);
                uint32_t b1 = uf(Ks[(nt * 8 + g) * 68 + kk + t + 4]);
                mma_tf32(c[nt], a, b0, b1);
            }
        }

        // Online softmax. Lane owns rows (g) via c0,c1 and (g+8) via c2,c3;
        // row is spread across the 4 lanes of a quad -> shfl_xor 1,2.
        float mx0 = -1e30f, mx1 = -1e30f;
#pragma unroll
        for (int nt = 0; nt < 8; nt++) {
            mx0 = fmaxf(mx0, fmaxf(c[nt][0], c[nt][1]));
            mx1 = fmaxf(mx1, fmaxf(c[nt][2], c[nt][3]));
        }
        mx0 *= scale; mx1 *= scale;
#pragma unroll
        for (int off = 1; off < 4; off <<= 1) {
            mx0 = fmaxf(mx0, __shfl_xor_sync(0xffffffffu, mx0, off));
            mx1 = fmaxf(mx1, __shfl_xor_sync(0xffffffffu, mx1, off));
        }
        float mn0 = fmaxf(mrow0, mx0), mn1 = fmaxf(mrow1, mx1);
        float corr0 = __expf(mrow0 - mn0), corr1 = __expf(mrow1 - mn1);
        float rs0 = 0.0f, rs1 = 0.0f;
#pragma unroll
        for (int nt = 0; nt < 8; nt++) {
            c[nt][0] = __expf(c[nt][0] * scale - mn0);
            c[nt][1] = __expf(c[nt][1] * scale - mn0);
            c[nt][2] = __expf(c[nt][2] * scale - mn1);
            c[nt][3] = __expf(c[nt][3] * scale - mn1);
            rs0 += c[nt][0] + c[nt][1];
            rs1 += c[nt][2] + c[nt][3];
        }
#pragma unroll
        for (int off = 1; off < 4; off <<= 1) {
            rs0 += __shfl_xor_sync(0xffffffffu, rs0, off);
            rs1 += __shfl_xor_sync(0xffffffffu, rs1, off);
        }
        lrow0 = lrow0 * corr0 + rs0;
        lrow1 = lrow1 * corr1 + rs1;
        mrow0 = mn0; mrow1 = mn1;
#pragma unroll
        for (int nt = 0; nt < 8; nt++) {
            o[nt][0] *= corr0; o[nt][1] *= corr0;
            o[nt][2] *= corr1; o[nt][3] *= corr1;
        }

        // Stage P (tf32) in per-warp smem, re-load as A fragments.
#pragma unroll
        for (int nt = 0; nt < 8; nt++) {
            float2 p01 = {f2tf32f(c[nt][0]), f2tf32f(c[nt][1])};
            float2 p23 = {f2tf32f(c[nt][2]), f2tf32f(c[nt][3])};
            *(float2*)&Pw[g * 68 + nt * 8 + 2 * t] = p01;
            *(float2*)&Pw[(g + 8) * 68 + nt * 8 + 2 * t] = p23;
        }
        __syncwarp();

        // O += P @ V   (k = 64 keys, n = 64 dims)
#pragma unroll
        for (int kt = 0; kt < 8; kt++) {
            int kk = kt * 8;
            uint32_t a[4];
            a[0] = uf(Pw[g * 68 + kk + t]);
            a[1] = uf(Pw[(g + 8) * 68 + kk + t]);
            a[2] = uf(Pw[g * 68 + kk + t + 4]);
            a[3] = uf(Pw[(g + 8) * 68 + kk + t + 4]);
#pragma unroll
            for (int nt = 0; nt < 8; nt++) {
                uint32_t b0 = uf(Vs[(kk + t) * 68 + nt * 8 + g]);
                uint32_t b1 = uf(Vs[(kk + t + 4) * 68 + nt * 8 + g]);
                mma_tf32(o[nt], a, b0, b1);
            }
        }
        __syncwarp();   // P reads done before next iteration overwrites
    }

    // Epilogue: normalize, write to g_o [B, N, DIM].
    const int bb = bh >> 4, h = bh & 15;
    const float inv0 = 1.0f / lrow0, inv1 = 1.0f / lrow1;
    const int row0 = i0 + w * 16 + g;
#pragma unroll
    for (int nt = 0; nt < 8; nt++) {
        int col = h * HDIM + nt * 8 + 2 * t;
        float2 v0 = {o[nt][0] * inv0, o[nt][1] * inv0};
        float2 v1 = {o[nt][2] * inv1, o[nt][3] * inv1};
        *(float2*)&g_o[(size_t)(bb * SEQ + row0) * DIM + col] = v0;
        *(float2*)&g_o[(size_t)(bb * SEQ + row0 + 8) * DIM + col] = v1;
    }
}

// ---------------------------------------------------------------------------
extern "C" void kernel_launch(void* const* d_in, const int* in_sizes, int n_in,
                              void* d_out, int out_size)
{
    const float* x      = (const float*)d_in[0];
    const float* sinp   = (const float*)d_in[1];
    const float* cosp   = (const float*)d_in[2];
    const float* W_qkv  = (const float*)d_in[3];
    const float* W_proj = (const float*)d_in[4];
    const float* b_proj = (const float*)d_in[5];
    float* out = (float*)d_out;

    static int init_done = 0;
    if (!init_done) {
        cudaFuncSetAttribute(flash_tf32_kernel,
                             cudaFuncAttributeMaxDynamicSharedMemorySize,
                             FA_SM_BYTES);
        init_done = 1;
    }

    // 1. QKV GEMM (tf32) with scatter into [B,H,N,HD].
    gemm_tf32_kernel<0><<<dim3(3 * DIM / 128, MTOT / 128), 256>>>(
        x, W_qkv, nullptr, nullptr);

    // 2. RoPE on q, k (fp32).
    {
        int total = BATCH * NHEADS * SEQ * 32;
        rope_kernel<<<(total + 255) / 256, 256>>>(sinp, cosp);
    }

    // 3. Flash attention (tf32 tensor cores).
    flash_tf32_kernel<<<dim3(SEQ / 128, BATCH * NHEADS), 256, FA_SM_BYTES>>>();

    // 4. Output projection + bias (tf32).
    gemm_tf32_kernel<1><<<dim3(DIM / 128, MTOT / 128), 256>>>(
        nullptr, W_proj, b_proj, out);
}

// round 3
// speedup vs baseline: 3.1740x; 1.3143x over previous
#include <cuda_runtime.h>
#include <cstdint>

#define DIM 1024
#define NHEADS 16
#define HDIM 64
#define BATCH 2
#define SEQ 2048
#define NROPE 2043
#define PREFIX (SEQ - NROPE)   // 5
#define MTOT (BATCH * SEQ)     // 4096

// Scratch — __device__ globals per allocation rules.
__device__ float g_q[BATCH * NHEADS * SEQ * HDIM];
__device__ float g_k[BATCH * NHEADS * SEQ * HDIM];
__device__ float g_v[BATCH * NHEADS * SEQ * HDIM];
__device__ float g_o[BATCH * SEQ * DIM];
__device__ float g_xt[MTOT * DIM];        // tf32 x
__device__ float g_wqt[DIM * 3 * DIM];    // tf32 W_qkv
__device__ float g_wpt[DIM * DIM];        // tf32 W_proj

// ---------------------------------------------------------------------------
// helpers
// ---------------------------------------------------------------------------
__device__ __forceinline__ float f2tf32f(float x) {
    uint32_t r;
    asm("cvt.rna.tf32.f32 %0, %1;" : "=r"(r) : "f"(x));
    return __uint_as_float(r);
}
__device__ __forceinline__ void mma_tf32(float* c, const uint32_t* a,
                                         uint32_t b0, uint32_t b1) {
    asm volatile(
        "mma.sync.aligned.m16n8k8.row.col.f32.tf32.tf32.f32 "
        "{%0,%1,%2,%3}, {%4,%5,%6,%7}, {%8,%9}, {%0,%1,%2,%3};"
        : "+f"(c[0]), "+f"(c[1]), "+f"(c[2]), "+f"(c[3])
        : "r"(a[0]), "r"(a[1]), "r"(a[2]), "r"(a[3]), "r"(b0), "r"(b1));
}
__device__ __forceinline__ uint32_t uf(float x) { return __float_as_uint(x); }
__device__ __forceinline__ void cp16(uint32_t dst, const void* src) {
    asm volatile("cp.async.cg.shared.global [%0], [%1], 16;"
                 :: "r"(dst), "l"(src));
}
__device__ __forceinline__ void cp_commit() {
    asm volatile("cp.async.commit_group;");
}
template <int N>
__device__ __forceinline__ void cp_wait() {
    asm volatile("cp.async.wait_group %0;" :: "n"(N));
}

// ---------------------------------------------------------------------------
// Prepack: convert x, W_qkv, W_proj to tf32 scratch (one-time per call).
// ---------------------------------------------------------------------------
#define XN4 (MTOT * DIM / 4)
#define WQ4 (DIM * 3 * DIM / 4)
#define WP4 (DIM * DIM / 4)
#define TOT4 (XN4 + WQ4 + WP4)

__global__ void prepack_kernel(const float4* __restrict__ x,
                               const float4* __restrict__ wq,
                               const float4* __restrict__ wp)
{
    int i = blockIdx.x * 256 + threadIdx.x;
    if (i >= TOT4) return;
    float4 v;
    float4* dst;
    if (i < XN4) { v = x[i]; dst = (float4*)g_xt + i; }
    else if (i < XN4 + WQ4) { int j = i - XN4; v = wq[j]; dst = (float4*)g_wqt + j; }
    else { int j = i - XN4 - WQ4; v = wp[j]; dst = (float4*)g_wpt + j; }
    v.x = f2tf32f(v.x); v.y = f2tf32f(v.y);
    v.z = f2tf32f(v.z); v.w = f2tf32f(v.w);
    *dst = v;
}

// ---------------------------------------------------------------------------
// TF32 GEMM with 4-stage cp.async pipeline. Block 128x128, BK=16, 8 warps.
// MODE 0: g_xt @ g_wqt -> fused RoPE -> scatter tf32 into g_q/g_k/g_v
// MODE 1: g_o  @ g_wpt -> + bias -> Cout (fp32)
// ---------------------------------------------------------------------------
#define G_STAGES 4
#define G_ASZ (128 * 20)
#define G_BSZ (16 * 136)
#define G_SM_FLOATS (G_STAGES * (G_ASZ + G_BSZ))
#define G_SM_BYTES (G_SM_FLOATS * 4)

template <int MODE>
__global__ __launch_bounds__(256, 2) void gemm_tf32_kernel(
    const float* __restrict__ bias, float* __restrict__ Cout,
    const float* __restrict__ sinp, const float* __restrict__ cosp)
{
    extern __shared__ float smp[];
    const int tid = threadIdx.x;
    const int lane = tid & 31, w = tid >> 5;
    const int g = lane >> 2, t = lane & 3;
    const int wm = w & 3, wn = w >> 2;
    const int m0 = blockIdx.y * 128, e0 = blockIdx.x * 128;
    const int ldb = (MODE == 0) ? (3 * DIM) : DIM;
    const float* Ap = (MODE == 0) ? g_xt : g_o;
    const float* Bp = (MODE == 0) ? g_wqt : g_wpt;

    const uint32_t sbase = (uint32_t)__cvta_generic_to_shared(smp);

    float acc[2][8][4];
#pragma unroll
    for (int i = 0; i < 2; i++)
#pragma unroll
        for (int j = 0; j < 8; j++)
#pragma unroll
            for (int q = 0; q < 4; q++) acc[i][j][q] = 0.0f;

    auto issue = [&](int s, int k0) {
#pragma unroll
        for (int r = 0; r < 2; r++) {
            int idx = tid + 256 * r;
            int row = idx >> 2, kc = (idx & 3) * 4;
            cp16(sbase + (uint32_t)(s * G_ASZ + row * 20 + kc) * 4,
                 Ap + (size_t)(m0 + row) * DIM + k0 + kc);
        }
#pragma unroll
        for (int r = 0; r < 2; r++) {
            int idx = tid + 256 * r;
            int row = idx >> 5, col = (idx & 31) * 4;
            cp16(sbase + (uint32_t)(G_STAGES * G_ASZ + s * G_BSZ +
                                    row * 136 + col) * 4,
                 Bp + (size_t)(k0 + row) * ldb + e0 + col);
        }
    };

    issue(0, 0);  cp_commit();
    issue(1, 16); cp_commit();
    issue(2, 32); cp_commit();

    for (int kt = 0; kt < DIM / 16; kt++) {
        cp_wait<G_STAGES - 2>();
        __syncthreads();
        int nk = kt + G_STAGES - 1;
        if (nk < DIM / 16) issue(nk & (G_STAGES - 1), nk * 16);
        cp_commit();

        const float* Asl = smp + (kt & (G_STAGES - 1)) * G_ASZ;
        const float* Bsl = smp + G_STAGES * G_ASZ + (kt & (G_STAGES - 1)) * G_BSZ;
#pragma unroll
        for (int kk = 0; kk < 16; kk += 8) {
            uint32_t a[2][4];
#pragma unroll
            for (int mi = 0; mi < 2; mi++) {
                int rb = wm * 32 + mi * 16;
                a[mi][0] = uf(Asl[(rb + g) * 20 + kk + t]);
                a[mi][1] = uf(Asl[(rb + g + 8) * 20 + kk + t]);
                a[mi][2] = uf(Asl[(rb + g) * 20 + kk + t + 4]);
                a[mi][3] = uf(Asl[(rb + g + 8) * 20 + kk + t + 4]);
            }
#pragma unroll
            for (int nt = 0; nt < 8; nt++) {
                int cb = wn * 64 + nt * 8 + g;
                uint32_t b0 = uf(Bsl[(kk + t) * 136 + cb]);
                uint32_t b1 = uf(Bsl[(kk + t + 4) * 136 + cb]);
                mma_tf32(acc[0][nt], a[0], b0, b1);
                mma_tf32(acc[1][nt], a[1], b0, b1);
            }
        }
    }

    // Epilogue
    if (MODE == 0) {
        const int which = e0 >> 10;
        const int h = ((e0 + wn * 64) >> 6) & 15;
        float* dst = (which == 0 ? g_q : (which == 1 ? g_k : g_v));
        const bool dorope = (which < 2);
#pragma unroll
        for (int mi = 0; mi < 2; mi++) {
#pragma unroll
            for (int half = 0; half < 2; half++) {
                int row = m0 + wm * 32 + mi * 16 + g + half * 8;
                int n = row & (SEQ - 1);
                int bb = row >> 11;
                int rp = n - PREFIX;
                bool rot = dorope && (n >= PREFIX);
                size_t base = ((size_t)(bb * NHEADS + h) * SEQ + n) * HDIM;
#pragma unroll
                for (int nt = 0; nt < 4; nt++) {
                    float lo[2], hi[2];
#pragma unroll
                    for (int j = 0; j < 2; j++) {
                        lo[j] = acc[mi][nt][half * 2 + j];
                        hi[j] = acc[mi][nt + 4][half * 2 + j];
                    }
                    if (rot) {
#pragma unroll
                        for (int j = 0; j < 2; j++) {
                            int hd = nt * 8 + 2 * t + j;
                            float c1 = __ldg(&cosp[rp * HDIM + hd]);
                            float s1 = __ldg(&sinp[rp * HDIM + hd]);
                            float c2 = __ldg(&cosp[rp * HDIM + hd + 32]);
                            float s2 = __ldg(&sinp[rp * HDIM + hd + 32]);
                            float nl = lo[j] * c1 - hi[j] * s1;
                            float nh = hi[j] * c2 + lo[j] * s2;
                            lo[j] = nl; hi[j] = nh;
                        }
                    }
                    float2 vlo = {f2tf32f(lo[0]), f2tf32f(lo[1])};
                    float2 vhi = {f2tf32f(hi[0]), f2tf32f(hi[1])};
                    *(float2*)&dst[base + nt * 8 + 2 * t] = vlo;
                    *(float2*)&dst[base + nt * 8 + 2 * t + 32] = vhi;
                }
            }
        }
    } else {
#pragma unroll
        for (int mi = 0; mi < 2; mi++) {
            int row0 = m0 + wm * 32 + mi * 16 + g;
#pragma unroll
            for (int nt = 0; nt < 8; nt++) {
                int e = e0 + wn * 64 + nt * 8 + 2 * t;
                float bx = bias[e], by = bias[e + 1];
                float2 v0 = {acc[mi][nt][0] + bx, acc[mi][nt][1] + by};
                float2 v1 = {acc[mi][nt][2] + bx, acc[mi][nt][3] + by};
                *(float2*)&Cout[(size_t)row0 * DIM + e] = v0;
                *(float2*)&Cout[(size_t)(row0 + 8) * DIM + e] = v1;
            }
        }
    }
}

// ---------------------------------------------------------------------------
// Flash attention, TF32 tensor cores, 2-stage cp.async KV pipeline.
// CTA: 8 warps; q-tile 128 (16 rows/warp); KV tiles of 64.
// smem floats: Qs 128*68, Ks 2*64*68, Vs 2*64*72, Pw 8*16*68
// ---------------------------------------------------------------------------
#define FA_QS 0
#define FA_KS (128 * 68)
#define FA_VS (FA_KS + 2 * 64 * 68)
#define FA_PS (FA_VS + 2 * 64 * 72)
#define FA_SM_FLOATS (FA_PS + 8 * 16 * 68)
#define FA_SM_BYTES (FA_SM_FLOATS * 4)
#define FA_NIT (SEQ / 64)

__global__ __launch_bounds__(256, 1) void flash_tf32_kernel()
{
    extern __shared__ float sm[];
    float* Qs = sm;
    const int tid = threadIdx.x;
    const int lane = tid & 31, w = tid >> 5;
    const int g = lane >> 2, t = lane & 3;
    float* Pw = sm + FA_PS + w * 16 * 68;
    const uint32_t sbase = (uint32_t)__cvta_generic_to_shared(sm);

    const int bh = blockIdx.y;
    const int i0 = blockIdx.x * 128;
    const float* qb = g_q + (size_t)bh * SEQ * HDIM;
    const float* kb = g_k + (size_t)bh * SEQ * HDIM;
    const float* vb = g_v + (size_t)bh * SEQ * HDIM;

    // Q tile (already tf32 in global).
#pragma unroll
    for (int r = 0; r < 8; r++) {
        int idx = tid + 256 * r;
        int row = idx >> 4, col = (idx & 15) * 4;
        *(float4*)&Qs[row * 68 + col] =
            *(const float4*)&qb[(size_t)(i0 + row) * HDIM + col];
    }

    auto issueKV = [&](int st, int j0) {
#pragma unroll
        for (int r = 0; r < 4; r++) {
            int idx = tid + 256 * r;
            int row = idx >> 4, col = (idx & 15) * 4;
            cp16(sbase + (uint32_t)(FA_KS + st * (64 * 68) + row * 68 + col) * 4,
                 kb + (size_t)(j0 + row) * HDIM + col);
            cp16(sbase + (uint32_t)(FA_VS + st * (64 * 72) + row * 72 + col) * 4,
                 vb + (size_t)(j0 + row) * HDIM + col);
        }
    };

    float o[8][4];
#pragma unroll
    for (int nt = 0; nt < 8; nt++)
#pragma unroll
        for (int q = 0; q < 4; q++) o[nt][q] = 0.0f;
    float mrow0 = -1e30f, mrow1 = -1e30f, lrow0 = 0.0f, lrow1 = 0.0f;
    const float scale = 0.125f;
    const int qb0 = w * 16;

    issueKV(0, 0);
    cp_commit();

    for (int it = 0; it < FA_NIT; it++) {
        cp_wait<0>();
        __syncthreads();
        if (it + 1 < FA_NIT) issueKV((it + 1) & 1, (it + 1) * 64);
        cp_commit();

        const float* Ks = sm + FA_KS + (it & 1) * (64 * 68);
        const float* Vs = sm + FA_VS + (it & 1) * (64 * 72);

        // S = Q @ K^T
        float c[8][4];
#pragma unroll
        for (int nt = 0; nt < 8; nt++)
#pragma unroll
            for (int q = 0; q < 4; q++) c[nt][q] = 0.0f;
#pragma unroll
        for (int kt = 0; kt < 8; kt++) {
            int kk = kt * 8;
            uint32_t a[4];
            a[0] = uf(Qs[(qb0 + g) * 68 + kk + t]);
            a[1] = uf(Qs[(qb0 + g + 8) * 68 + kk + t]);
            a[2] = uf(Qs[(qb0 + g) * 68 + kk + t + 4]);
            a[3] = uf(Qs[(qb0 + g + 8) * 68 + kk + t + 4]);
#pragma unroll
            for (int nt = 0; nt < 8; nt++) {
                uint32_t b0 = uf(Ks[(nt * 8 + g) * 68 + kk + t]);
                uint32_t b1 = uf(Ks[(nt * 8 + g) * 68 + kk + t + 4]);
                mma_tf32(c[nt], a, b0, b1);
            }
        }

        // Online softmax (row spread across lane quad -> shfl_xor 1,2).
        float mx0 = -1e30f, mx1 = -1e30f;
#pragma unroll
        for (int nt = 0; nt < 8; nt++) {
            mx0 = fmaxf(mx0, fmaxf(c[nt][0], c[nt][1]));
            mx1 = fmaxf(mx1, fmaxf(c[nt][2], c[nt][3]));
        }
        mx0 *= scale; mx1 *= scale;
#pragma unroll
        for (int off = 1; off < 4; off <<= 1) {
            mx0 = fmaxf(mx0, __shfl_xor_sync(0xffffffffu, mx0, off));
            mx1 = fmaxf(mx1, __shfl_xor_sync(0xffffffffu, mx1, off));
        }
        float mn0 = fmaxf(mrow0, mx0), mn1 = fmaxf(mrow1, mx1);
        float corr0 = __expf(mrow0 - mn0), corr1 = __expf(mrow1 - mn1);
        float rs0 = 0.0f, rs1 = 0.0f;
#pragma unroll
        for (int nt = 0; nt < 8; nt++) {
            c[nt][0] = __expf(c[nt][0] * scale - mn0);
            c[nt][1] = __expf(c[nt][1] * scale - mn0);
            c[nt][2] = __expf(c[nt][2] * scale - mn1);
            c[nt][3] = __expf(c[nt][3] * scale - mn1);
            rs0 += c[nt][0] + c[nt][1];
            rs1 += c[nt][2] + c[nt][3];
        }
#pragma unroll
        for (int off = 1; off < 4; off <<= 1) {
            rs0 += __shfl_xor_sync(0xffffffffu, rs0, off);
            rs1 += __shfl_xor_sync(0xffffffffu, rs1, off);
        }
        lrow0 = lrow0 * corr0 + rs0;
        lrow1 = lrow1 * corr1 + rs1;
        mrow0 = mn0; mrow1 = mn1;
#pragma unroll
        for (int nt = 0; nt < 8; nt++) {
            o[nt][0] *= corr0; o[nt][1] *= corr0;
            o[nt][2] *= corr1; o[nt][3] *= corr1;
        }

        // Stage P (tf32) in per-warp smem.
#pragma unroll
        for (int nt = 0; nt < 8; nt++) {
            float2 p01 = {f2tf32f(c[nt][0]), f2tf32f(c[nt][1])};
            float2 p23 = {f2tf32f(c[nt][2]), f2tf32f(c[nt][3])};
            *(float2*)&Pw[g * 68 + nt * 8 + 2 * t] = p01;
            *(float2*)&Pw[(g + 8) * 68 + nt * 8 + 2 * t] = p23;
        }
        __syncwarp();

        // O += P @ V
#pragma unroll
        for (int kt = 0; kt < 8; kt++) {
            int kk = kt * 8;
            uint32_t a[4];
            a[0] = uf(Pw[g * 68 + kk + t]);
            a[1] = uf(Pw[(g + 8) * 68 + kk + t]);
            a[2] = uf(Pw[g * 68 + kk + t + 4]);
            a[3] = uf(Pw[(g + 8) * 68 + kk + t + 4]);
#pragma unroll
            for (int nt = 0; nt < 8; nt++) {
                uint32_t b0 = uf(Vs[(kk + t) * 72 + nt * 8 + g]);
                uint32_t b1 = uf(Vs[(kk + t + 4) * 72 + nt * 8 + g]);
                mma_tf32(o[nt], a, b0, b1);
            }
        }
        __syncwarp();
    }

    // Epilogue: normalize, store tf32 into g_o [B, N, DIM] (feeds proj GEMM).
    const int bb = bh >> 4, h = bh & 15;
    const float inv0 = 1.0f / lrow0, inv1 = 1.0f / lrow1;
    const int row0 = i0 + w * 16 + g;
#pragma unroll
    for (int nt = 0; nt < 8; nt++) {
        int col = h * HDIM + nt * 8 + 2 * t;
        float2 v0 = {f2tf32f(o[nt][0] * inv0), f2tf32f(o[nt][1] * inv0)};
        float2 v1 = {f2tf32f(o[nt][2] * inv1), f2tf32f(o[nt][3] * inv1)};
        *(float2*)&g_o[(size_t)(bb * SEQ + row0) * DIM + col] = v0;
        *(float2*)&g_o[(size_t)(bb * SEQ + row0 + 8) * DIM + col] = v1;
    }
}

// ---------------------------------------------------------------------------
extern "C" void kernel_launch(void* const* d_in, const int* in_sizes, int n_in,
                              void* d_out, int out_size)
{
    const float* x      = (const float*)d_in[0];
    const float* sinp   = (const float*)d_in[1];
    const float* cosp   = (const float*)d_in[2];
    const float* W_qkv  = (const float*)d_in[3];
    const float* W_proj = (const float*)d_in[4];
    const float* b_proj = (const float*)d_in[5];
    float* out = (float*)d_out;

    static int init_done = 0;
    if (!init_done) {
        cudaFuncSetAttribute(flash_tf32_kernel,
                             cudaFuncAttributeMaxDynamicSharedMemorySize,
                             FA_SM_BYTES);
        cudaFuncSetAttribute(gemm_tf32_kernel<0>,
                             cudaFuncAttributeMaxDynamicSharedMemorySize,
                             G_SM_BYTES);
        cudaFuncSetAttribute(gemm_tf32_kernel<1>,
                             cudaFuncAttributeMaxDynamicSharedMemorySize,
                             G_SM_BYTES);
        init_done = 1;
    }

    // 0. Prepack inputs/weights to tf32 scratch.
    prepack_kernel<<<(TOT4 + 255) / 256, 256>>>(
        (const float4*)x, (const float4*)W_qkv, (const float4*)W_proj);

    // 1. QKV GEMM + fused RoPE, scatter tf32 into [B,H,N,HD].
    gemm_tf32_kernel<0><<<dim3(3 * DIM / 128, MTOT / 128), 256, G_SM_BYTES>>>(
        nullptr, nullptr, sinp, cosp);

    // 2. Flash attention (tf32 tensor cores, cp.async double buffer).
    flash_tf32_kernel<<<dim3(SEQ / 128, BATCH * NHEADS), 256, FA_SM_BYTES>>>();

    // 3. Output projection + bias.
    gemm_tf32_kernel<1><<<dim3(DIM / 128, MTOT / 128), 256, G_SM_BYTES>>>(
        b_proj, out, nullptr, nullptr);
}